// round 13
// baseline (speedup 1.0000x reference)
#include <cuda_runtime.h>
#include <cstdint>
#include <cstddef>

#define Bn   128
#define Sn   256
#define GM   (Bn*Sn)         // 32768
#define NEGV (-10000.0f)

typedef unsigned long long u64;

// ---------------- scratch (device globals; no allocation allowed) ----------------
__device__ float g_x [GM*130];            // concat(word_emb, char_feat)
__device__ float g_wt[130*800];           // transposed input weights [k][n]
__device__ float g_xw[2u*GM*400];         // x @ wih^T + (bih+bhh), per direction
__device__ float g_h [2u*GM*100];         // hidden states f/b
__device__ float g_em[GM*32];             // emissions
__device__ float g_P [100*96];            // char-conv table [c][k*32+f]

__device__ __forceinline__ float mtanh(float x){
    float r; asm("tanh.approx.f32 %0, %1;" : "=f"(r) : "f"(x)); return r;
}
__device__ __forceinline__ float msigm(float x){ return fmaf(mtanh(0.5f*x), 0.5f, 0.5f); }

// packed f32x2 helpers (Blackwell; ptxas never auto-fuses these)
__device__ __forceinline__ void fma2(u64 &d, u64 a, u64 b){
    asm("fma.rn.f32x2 %0, %1, %2, %0;" : "+l"(d) : "l"(a), "l"(b));
}
__device__ __forceinline__ u64 pack2(float x, float y){
    u64 r; asm("mov.b64 %0, {%1, %2};" : "=l"(r) : "f"(x), "f"(y)); return r;
}
__device__ __forceinline__ float2 unpack2(u64 v){
    float2 r; asm("mov.b64 {%0, %1}, %2;" : "=f"(r.x), "=f"(r.y) : "l"(v)); return r;
}

// ---------------- kernel 0: prep = char-conv table + weight transpose ----------------
__global__ __launch_bounds__(256) void k_prep(
    const float* __restrict__ conv_w, const float* __restrict__ char_emb,
    const float* __restrict__ wih_f,  const float* __restrict__ wih_b)
{
    int idx = blockIdx.x*256 + threadIdx.x;
    if (idx < 9600){                              // P table: 100*96
        int c = idx / 96, r = idx % 96, k = r >> 5, f = r & 31;
        float s = 0.0f;
        if (f < 30){
            const float* w = conv_w + f*90 + k*30;
            const float* e = char_emb + c*30;
#pragma unroll
            for (int d=0; d<30; d++) s += w[d]*e[d];
        }
        g_P[idx] = s;
    }
    int idx2 = idx - 9600;                        // wt: 130*800
    if (idx2 >= 0 && idx2 < 130*800){
        int k = idx2 / 800, n = idx2 % 800;
        g_wt[idx2] = (n < 400) ? wih_f[(size_t)n*130 + k] : wih_b[(size_t)(n-400)*130 + k];
    }
}

// ---------------- kernel 1: embedding concat + table-lookup char CNN -> g_x ----------------
__global__ __launch_bounds__(256) void k_cnn(
    const float* __restrict__ word_emb, const float* __restrict__ conv_b,
    const int*   __restrict__ word_x,   const int*   __restrict__ char_x)
{
    __shared__ float sP[9600];
    __shared__ float sb[32];

    int tid  = threadIdx.x;
    int lane = tid & 31;
    int wrp  = tid >> 5;

    for (int i = tid; i < 9600; i += 256) sP[i] = g_P[i];
    if (tid < 30) sb[tid] = conv_b[tid];
    __syncthreads();

    int base = blockIdx.x*64 + wrp*8;
#pragma unroll
    for (int i=0;i<8;i++){
        int bs = base + i;

        int cv = 0;
        if (lane < 10) cv = char_x[bs*10 + lane];

        int wid = word_x[bs];
        const float* wrow = word_emb + (size_t)wid*100;
        float* xo = g_x + (size_t)bs*130;
        for (int t = lane; t < 100; t += 32) xo[t] = wrow[t];

        int ci[10];
#pragma unroll
        for (int l=0;l<10;l++)
            ci[l] = __shfl_sync(0xffffffffu, cv, l)*96 + lane;

        float best = -1e30f;
#pragma unroll
        for (int p=0;p<12;p++){
            float acc = 0.0f;
            if (p >= 2)           acc += sP[ci[p-2] +  0];
            if (p >= 1 && p <=10) acc += sP[ci[p-1] + 32];
            if (p <= 9)           acc += sP[ci[p]   + 64];
            best = fmaxf(best, acc);
        }
        if (lane < 30) xo[100 + lane] = best + sb[lane];
    }
}

// ---------------- kernel 2: input-projection SGEMM v3b -> g_xw ----------------
__global__ __launch_bounds__(256,2) void k_gemm_in(
    const float* __restrict__ bih_f, const float* __restrict__ bhh_f,
    const float* __restrict__ bih_b, const float* __restrict__ bhh_b)
{
    __shared__ float2 As2[64*66];    // [mp][k]  rows (2mp, 2mp+1)
    __shared__ u64    Bs2[65*130];   // [k][nl]  duplicated (b,b), stride 130 (16B-aligned)

    int tid = threadIdx.x;
    int m0 = blockIdx.y*128;
    int n0 = blockIdx.x*128;
    int tx = tid & 15, ty = tid >> 4;

    u64 acc[4][8];
#pragma unroll
    for (int r=0;r<4;r++)
#pragma unroll
        for (int c=0;c<8;c++) acc[r][c] = 0ull;

    for (int k0=0; k0<130; k0+=65){
        for (int idx=tid; idx<64*65; idx+=256){
            int mp = idx/65, k = idx%65;
            float lo = g_x[(size_t)(m0+2*mp  )*130 + k0 + k];
            float hi = g_x[(size_t)(m0+2*mp+1)*130 + k0 + k];
            As2[mp*66 + k] = make_float2(lo, hi);
        }
        for (int idx=tid; idx<65*128; idx+=256){
            int k = idx >> 7, nl = idx & 127;
            int n = n0+nl;
            float v = (n < 800) ? g_wt[(size_t)(k0+k)*800 + n] : 0.0f;
            Bs2[k*130 + nl] = pack2(v, v);
        }
        __syncthreads();
#pragma unroll 5
        for (int k=0;k<65;k++){
            u64 a0 = *(const u64*)&As2[(ty*4+0)*66 + k];
            u64 a1 = *(const u64*)&As2[(ty*4+1)*66 + k];
            u64 a2 = *(const u64*)&As2[(ty*4+2)*66 + k];
            u64 a3 = *(const u64*)&As2[(ty*4+3)*66 + k];
            ulonglong2 bg0 = *(const ulonglong2*)&Bs2[k*130 + tx*2      ];
            ulonglong2 bg1 = *(const ulonglong2*)&Bs2[k*130 + tx*2 + 32 ];
            ulonglong2 bg2 = *(const ulonglong2*)&Bs2[k*130 + tx*2 + 64 ];
            ulonglong2 bg3 = *(const ulonglong2*)&Bs2[k*130 + tx*2 + 96 ];
            fma2(acc[0][0], a0, bg0.x); fma2(acc[0][1], a0, bg0.y);
            fma2(acc[0][2], a0, bg1.x); fma2(acc[0][3], a0, bg1.y);
            fma2(acc[0][4], a0, bg2.x); fma2(acc[0][5], a0, bg2.y);
            fma2(acc[0][6], a0, bg3.x); fma2(acc[0][7], a0, bg3.y);
            fma2(acc[1][0], a1, bg0.x); fma2(acc[1][1], a1, bg0.y);
            fma2(acc[1][2], a1, bg1.x); fma2(acc[1][3], a1, bg1.y);
            fma2(acc[1][4], a1, bg2.x); fma2(acc[1][5], a1, bg2.y);
            fma2(acc[1][6], a1, bg3.x); fma2(acc[1][7], a1, bg3.y);
            fma2(acc[2][0], a2, bg0.x); fma2(acc[2][1], a2, bg0.y);
            fma2(acc[2][2], a2, bg1.x); fma2(acc[2][3], a2, bg1.y);
            fma2(acc[2][4], a2, bg2.x); fma2(acc[2][5], a2, bg2.y);
            fma2(acc[2][6], a2, bg3.x); fma2(acc[2][7], a2, bg3.y);
            fma2(acc[3][0], a3, bg0.x); fma2(acc[3][1], a3, bg0.y);
            fma2(acc[3][2], a3, bg1.x); fma2(acc[3][3], a3, bg1.y);
            fma2(acc[3][4], a3, bg2.x); fma2(acc[3][5], a3, bg2.y);
            fma2(acc[3][6], a3, bg3.x); fma2(acc[3][7], a3, bg3.y);
        }
        __syncthreads();
    }

#pragma unroll
    for (int r=0;r<4;r++)
#pragma unroll
        for (int c=0;c<8;c++){
            int g = c >> 1, p = c & 1;
            int n = n0 + g*32 + tx*2 + p;
            if (n < 800){
                int dir = n/400, jj = n%400;
                float bias = dir ? (bih_b[jj]+bhh_b[jj]) : (bih_f[jj]+bhh_f[jj]);
                float2 v = unpack2(acc[r][c]);
                int m = m0 + 2*(ty*4 + r);
                float* dst = g_xw + (size_t)dir*GM*400 + (size_t)m*400 + jj;
                dst[0]   = v.x + bias;
                dst[400] = v.y + bias;
            }
        }
}

// ---------------- kernel 3: LSTM, TWO independent groups per block (named barriers) ----------------
// 832 threads = 26 warps = 2 warp-aligned groups of 416 (400 active).
// Group g runs batch 2*pr+g full-row (whh row in regs), with its OWN named
// barrier (bar.sync g+1, 416). Groups share no state: one group's act/barrier
// bubble is covered by the other group's matvec issue.
__global__ __launch_bounds__(832,1) void k_lstm(
    const float* __restrict__ whh_f, const float* __restrict__ whh_b)
{
    int bx  = blockIdx.x;
    int dir = bx >> 6;
    int pr  = bx & 63;
    int tid = threadIdx.x;
    int grp = (tid >= 416);
    int lt  = tid - grp*416;          // 0..415 within group
    int b   = pr*2 + grp;
    int barid = grp + 1;
    bool active = (lt < 400);
    int j = active ? lt : 0;          // gate row

    const float* whh = dir ? whh_b : whh_f;
    const ulonglong2* wrow = (const ulonglong2*)(whh + (size_t)j*100);
    ulonglong2 w[25];
#pragma unroll
    for (int q=0;q<25;q++) w[q] = wrow[q];

    __shared__ float h_s[2][112];     // [grp][100] (stride 112 keeps rows 16B-aligned)
    __shared__ float sp [2][400];     // [grp][gate]
    if (tid < 224) ((float*)h_s)[tid] = 0.0f;
    float c_reg = 0.0f;

    int t0 = dir ? 255 : 0;
    int dstep  = dir ? -400 : 400;
    int dsteph = dir ? -100 : 100;

    const float* xwp = g_xw + (size_t)dir*GM*400 + (size_t)(b*256+t0)*400 + j;
    float* houtp = g_h + (size_t)dir*GM*100 + (size_t)(b*256+t0)*100 + (lt < 100 ? lt : 0);

    __syncthreads();                  // h_s init visible to both groups' threads

    float av = active ? *xwp : 0.0f;

    for (int step=0; step<256; step++){
        float nav = 0.0f;
        if (active && step < 255) nav = xwp[dstep];
        xwp += dstep;

        if (active){
            u64 s0 = 0ull, s1 = 0ull;
#pragma unroll
            for (int q=0;q<25;q++){
                ulonglong2 wq = w[q];
                ulonglong2 hh = *(const ulonglong2*)&h_s[grp][q*4];
                fma2(s0, wq.x, hh.x);
                fma2(s1, wq.y, hh.y);
            }
            float2 u0 = unpack2(s0), u1 = unpack2(s1);
            sp[grp][j] = av + ((u0.x+u0.y)+(u1.x+u1.y));
        }
        asm volatile("bar.sync %0, 416;" :: "r"(barid) : "memory");

        if (lt < 100){
            float gi = sp[grp][lt];
            float gf = sp[grp][100+lt];
            float gg = sp[grp][200+lt];
            float go = sp[grp][300+lt];
            float ct = msigm(gf)*c_reg + msigm(gi)*mtanh(gg);
            c_reg = ct;
            float h = msigm(go)*mtanh(ct);
            h_s[grp][lt] = h;
            *houtp = h;
            houtp += dsteph;
        }
        asm volatile("bar.sync %0, 416;" :: "r"(barid) : "memory");
        av = nav;
    }
}

// ---------------- kernel 4: emission projection (tiled) -> g_em ----------------
__global__ __launch_bounds__(256) void k_emis(
    const float* __restrict__ proj_w, const float* __restrict__ proj_b)
{
    __shared__ float hs[64*204];   // [m][k] padded row stride
    __shared__ float pw[200*32];   // [k][tag]
    __shared__ float pb[32];

    int tid = threadIdx.x;
    int bs0 = blockIdx.x*64;

    for (int idx=tid; idx<6400; idx+=256){
        int tag = idx/200, k = idx%200;
        pw[k*32+tag] = proj_w[idx];
    }
    if (tid < 32) pb[tid] = proj_b[tid];

    for (int idx=tid; idx<64*50; idx+=256){
        int m = idx/50, q = idx%50;
        int bs = bs0 + m;
        const float* src = (q < 25) ? (g_h + (size_t)bs*100 + q*4)
                                    : (g_h + (size_t)GM*100 + (size_t)bs*100 + (q-25)*4);
        float4 v = *(const float4*)src;
        *(float4*)&hs[m*204 + q*4] = v;
    }
    __syncthreads();

    int tag  = tid & 31;
    int msub = tid >> 5;           // 0..7

    float acc[8];
#pragma unroll
    for (int i=0;i<8;i++) acc[i] = pb[tag];

    for (int k=0;k<200;k++){
        float pwv = pw[k*32 + tag];
#pragma unroll
        for (int i=0;i<8;i++)
            acc[i] += hs[(msub + 8*i)*204 + k] * pwv;   // broadcast read
    }
#pragma unroll
    for (int i=0;i<8;i++)
        g_em[(size_t)(bs0 + msub + 8*i)*32 + tag] = acc[i];
}

// ---------------- kernel 5: CRF (exp-factorized, lane0-normalized, split sums) ----------------
__global__ __launch_bounds__(32) void k_crf(
    const float* __restrict__ trans, const int* __restrict__ y, float* __restrict__ out)
{
    __shared__ float E_s[32];
    int j = threadIdx.x, b = blockIdx.x;

    float T[32];
#pragma unroll
    for (int i=0;i<32;i++) T[i] = __expf(trans[i*32 + j]);   // exp(NEG)=0, safe
    float tend = trans[j*32 + 31];                           // trans[j, END]

    float score = 0.0f;
    for (int t=j; t<256; t+=32){
        int cur  = y[b*256+t];
        int prev = (t==0) ? 30 : y[b*256+t-1];
        score += g_em[(size_t)(b*256+t)*32 + cur] + trans[prev*32+cur];
    }
    __syncwarp();

    float la  = g_em[(size_t)(b*256)*32 + j] + trans[30*32 + j];
    float emv = g_em[(size_t)(b*256+1)*32 + j];

    for (int t=1; t<256; t++){
        float em_next = (t < 255) ? g_em[(size_t)(b*256+t+1)*32 + j] : 0.0f;

        float m = __shfl_sync(0xffffffffu, la, 0);
        E_s[j] = __expf(la - m);
        __syncwarp();
        float s0=0.f, s1=0.f, s2=0.f, s3=0.f;
#pragma unroll
        for (int i=0;i<8;i++){
            s0 += E_s[i   ]*T[i   ];
            s1 += E_s[i+ 8]*T[i+ 8];
            s2 += E_s[i+16]*T[i+16];
            s3 += E_s[i+24]*T[i+24];
        }
        la = emv + m + __logf((s0+s1)+(s2+s3));
        __syncwarp();
        emv = em_next;
    }

    la += tend;
    float m = la;
#pragma unroll
    for (int o=16;o>0;o>>=1) m = fmaxf(m, __shfl_xor_sync(0xffffffffu, m, o));
    float e = __expf(la - m);
#pragma unroll
    for (int o=16;o>0;o>>=1) e += __shfl_xor_sync(0xffffffffu, e, o);
    float total = m + __logf(e);

#pragma unroll
    for (int o=16;o>0;o>>=1) score += __shfl_xor_sync(0xffffffffu, score, o);

    if (j==0){
        score += trans[y[b*256+255]*32 + 31];
        atomicAdd(out, (total - score) * (1.0f/128.0f));
    }
}

// ---------------- launch ----------------
extern "C" void kernel_launch(void* const* d_in, const int* in_sizes, int n_in,
                              void* d_out, int out_size)
{
    const float* word_emb = (const float*)d_in[0];
    const float* char_emb = (const float*)d_in[1];
    const float* conv_w   = (const float*)d_in[2];
    const float* conv_b   = (const float*)d_in[3];
    const float* wih_f    = (const float*)d_in[4];
    const float* whh_f    = (const float*)d_in[5];
    const float* bih_f    = (const float*)d_in[6];
    const float* bhh_f    = (const float*)d_in[7];
    const float* wih_b    = (const float*)d_in[8];
    const float* whh_b    = (const float*)d_in[9];
    const float* bih_b    = (const float*)d_in[10];
    const float* bhh_b    = (const float*)d_in[11];
    const float* proj_w   = (const float*)d_in[12];
    const float* proj_b   = (const float*)d_in[13];
    const float* trans    = (const float*)d_in[14];
    const int*   word_x   = (const int*)d_in[15];
    const int*   char_x   = (const int*)d_in[16];
    const int*   y        = (const int*)d_in[17];
    float* out = (float*)d_out;

    k_prep<<<(9600+130*800+255)/256,256>>>(conv_w, char_emb, wih_f, wih_b);
    k_cnn<<<512,256>>>(word_emb, conv_b, word_x, char_x);
    dim3 gg(7, 256);
    k_gemm_in<<<gg,256>>>(bih_f, bhh_f, bih_b, bhh_b);
    k_lstm<<<128,832>>>(whh_f, whh_b);
    k_emis<<<512,256>>>(proj_w, proj_b);
    cudaMemsetAsync(out, 0, sizeof(float));
    k_crf<<<128,32>>>(trans, y, out);
}

// round 14
// speedup vs baseline: 2.1664x; 2.1664x over previous
#include <cuda_runtime.h>
#include <cstdint>
#include <cstddef>

#define Bn   128
#define Sn   256
#define GM   (Bn*Sn)         // 32768
#define NEGV (-10000.0f)

typedef unsigned long long u64;

// ---------------- scratch (device globals; no allocation allowed) ----------------
__device__ float g_x [GM*130];            // concat(word_emb, char_feat)
__device__ float g_wt[130*800];           // transposed input weights [k][n]
__device__ float g_xw[2u*GM*400];         // x @ wih^T + (bih+bhh), per direction
__device__ float g_h [2u*GM*100];         // hidden states f/b
__device__ float g_em[GM*32];             // emissions
__device__ float g_P [100*96];            // char-conv table [c][k*32+f]

__device__ __forceinline__ float mtanh(float x){
    float r; asm("tanh.approx.f32 %0, %1;" : "=f"(r) : "f"(x)); return r;
}
__device__ __forceinline__ float msigm(float x){ return fmaf(mtanh(0.5f*x), 0.5f, 0.5f); }

// packed f32x2 helpers (Blackwell; ptxas never auto-fuses these)
__device__ __forceinline__ void fma2(u64 &d, u64 a, u64 b){
    asm("fma.rn.f32x2 %0, %1, %2, %0;" : "+l"(d) : "l"(a), "l"(b));
}
__device__ __forceinline__ u64 pack2(float x, float y){
    u64 r; asm("mov.b64 %0, {%1, %2};" : "=l"(r) : "f"(x), "f"(y)); return r;
}
__device__ __forceinline__ float2 unpack2(u64 v){
    float2 r; asm("mov.b64 {%0, %1}, %2;" : "=f"(r.x), "=f"(r.y) : "l"(v)); return r;
}

// ---------------- kernel 0: prep = char-conv table + weight transpose ----------------
__global__ __launch_bounds__(256) void k_prep(
    const float* __restrict__ conv_w, const float* __restrict__ char_emb,
    const float* __restrict__ wih_f,  const float* __restrict__ wih_b)
{
    int idx = blockIdx.x*256 + threadIdx.x;
    if (idx < 9600){                              // P table: 100*96
        int c = idx / 96, r = idx % 96, k = r >> 5, f = r & 31;
        float s = 0.0f;
        if (f < 30){
            const float* w = conv_w + f*90 + k*30;
            const float* e = char_emb + c*30;
#pragma unroll
            for (int d=0; d<30; d++) s += w[d]*e[d];
        }
        g_P[idx] = s;
    }
    int idx2 = idx - 9600;                        // wt: 130*800
    if (idx2 >= 0 && idx2 < 130*800){
        int k = idx2 / 800, n = idx2 % 800;
        g_wt[idx2] = (n < 400) ? wih_f[(size_t)n*130 + k] : wih_b[(size_t)(n-400)*130 + k];
    }
}

// ---------------- kernel 1: embedding concat + table-lookup char CNN -> g_x ----------------
__global__ __launch_bounds__(256) void k_cnn(
    const float* __restrict__ word_emb, const float* __restrict__ conv_b,
    const int*   __restrict__ word_x,   const int*   __restrict__ char_x)
{
    __shared__ float sP[9600];
    __shared__ float sb[32];

    int tid  = threadIdx.x;
    int lane = tid & 31;
    int wrp  = tid >> 5;

    for (int i = tid; i < 9600; i += 256) sP[i] = g_P[i];
    if (tid < 30) sb[tid] = conv_b[tid];
    __syncthreads();

    int base = blockIdx.x*64 + wrp*8;
#pragma unroll
    for (int i=0;i<8;i++){
        int bs = base + i;

        int cv = 0;
        if (lane < 10) cv = char_x[bs*10 + lane];

        int wid = word_x[bs];
        const float* wrow = word_emb + (size_t)wid*100;
        float* xo = g_x + (size_t)bs*130;
        for (int t = lane; t < 100; t += 32) xo[t] = wrow[t];

        int ci[10];
#pragma unroll
        for (int l=0;l<10;l++)
            ci[l] = __shfl_sync(0xffffffffu, cv, l)*96 + lane;

        float best = -1e30f;
#pragma unroll
        for (int p=0;p<12;p++){
            float acc = 0.0f;
            if (p >= 2)           acc += sP[ci[p-2] +  0];
            if (p >= 1 && p <=10) acc += sP[ci[p-1] + 32];
            if (p <= 9)           acc += sP[ci[p]   + 64];
            best = fmaxf(best, acc);
        }
        if (lane < 30) xo[100 + lane] = best + sb[lane];
    }
}

// ---------------- kernel 2: input-projection SGEMM v3b -> g_xw ----------------
// 128(m) x 128(n) tile, 256 threads, 2 blocks/SM.
// A smem [mp][k] float2 (coalesced staging along k, LDS.64 broadcast reads).
// B smem [k][nl] u64 PRE-DUPLICATED, row stride 130 (EVEN -> 16B-aligned rows).
// Thread's 8 columns strided: {g*32 + tx*2 + p : g<4, p<2} -> conflict-free LDS.128.
__global__ __launch_bounds__(256,2) void k_gemm_in(
    const float* __restrict__ bih_f, const float* __restrict__ bhh_f,
    const float* __restrict__ bih_b, const float* __restrict__ bhh_b)
{
    __shared__ float2 As2[64*66];    // [mp][k]  rows (2mp, 2mp+1)
    __shared__ u64    Bs2[65*130];   // [k][nl]  duplicated (b,b), stride 130 (16B-aligned)

    int tid = threadIdx.x;
    int m0 = blockIdx.y*128;
    int n0 = blockIdx.x*128;
    int tx = tid & 15, ty = tid >> 4;

    u64 acc[4][8];
#pragma unroll
    for (int r=0;r<4;r++)
#pragma unroll
        for (int c=0;c<8;c++) acc[r][c] = 0ull;

    for (int k0=0; k0<130; k0+=65){
        // A: consecutive threads -> consecutive k (coalesced LDG)
        for (int idx=tid; idx<64*65; idx+=256){
            int mp = idx/65, k = idx%65;
            float lo = g_x[(size_t)(m0+2*mp  )*130 + k0 + k];
            float hi = g_x[(size_t)(m0+2*mp+1)*130 + k0 + k];
            As2[mp*66 + k] = make_float2(lo, hi);
        }
        // B: consecutive threads -> consecutive nl (coalesced LDG + STS.64)
        for (int idx=tid; idx<65*128; idx+=256){
            int k = idx >> 7, nl = idx & 127;
            int n = n0+nl;
            float v = (n < 800) ? g_wt[(size_t)(k0+k)*800 + n] : 0.0f;
            Bs2[k*130 + nl] = pack2(v, v);
        }
        __syncthreads();
#pragma unroll 5
        for (int k=0;k<65;k++){
            u64 a0 = *(const u64*)&As2[(ty*4+0)*66 + k];
            u64 a1 = *(const u64*)&As2[(ty*4+1)*66 + k];
            u64 a2 = *(const u64*)&As2[(ty*4+2)*66 + k];
            u64 a3 = *(const u64*)&As2[(ty*4+3)*66 + k];
            // strided column groups: 16 lanes read 256B contiguous per LDS.128
            ulonglong2 bg0 = *(const ulonglong2*)&Bs2[k*130 + tx*2      ];
            ulonglong2 bg1 = *(const ulonglong2*)&Bs2[k*130 + tx*2 + 32 ];
            ulonglong2 bg2 = *(const ulonglong2*)&Bs2[k*130 + tx*2 + 64 ];
            ulonglong2 bg3 = *(const ulonglong2*)&Bs2[k*130 + tx*2 + 96 ];
            fma2(acc[0][0], a0, bg0.x); fma2(acc[0][1], a0, bg0.y);
            fma2(acc[0][2], a0, bg1.x); fma2(acc[0][3], a0, bg1.y);
            fma2(acc[0][4], a0, bg2.x); fma2(acc[0][5], a0, bg2.y);
            fma2(acc[0][6], a0, bg3.x); fma2(acc[0][7], a0, bg3.y);
            fma2(acc[1][0], a1, bg0.x); fma2(acc[1][1], a1, bg0.y);
            fma2(acc[1][2], a1, bg1.x); fma2(acc[1][3], a1, bg1.y);
            fma2(acc[1][4], a1, bg2.x); fma2(acc[1][5], a1, bg2.y);
            fma2(acc[1][6], a1, bg3.x); fma2(acc[1][7], a1, bg3.y);
            fma2(acc[2][0], a2, bg0.x); fma2(acc[2][1], a2, bg0.y);
            fma2(acc[2][2], a2, bg1.x); fma2(acc[2][3], a2, bg1.y);
            fma2(acc[2][4], a2, bg2.x); fma2(acc[2][5], a2, bg2.y);
            fma2(acc[2][6], a2, bg3.x); fma2(acc[2][7], a2, bg3.y);
            fma2(acc[3][0], a3, bg0.x); fma2(acc[3][1], a3, bg0.y);
            fma2(acc[3][2], a3, bg1.x); fma2(acc[3][3], a3, bg1.y);
            fma2(acc[3][4], a3, bg2.x); fma2(acc[3][5], a3, bg2.y);
            fma2(acc[3][6], a3, bg3.x); fma2(acc[3][7], a3, bg3.y);
        }
        __syncthreads();
    }

#pragma unroll
    for (int r=0;r<4;r++)
#pragma unroll
        for (int c=0;c<8;c++){
            int g = c >> 1, p = c & 1;
            int n = n0 + g*32 + tx*2 + p;
            if (n < 800){
                int dir = n/400, jj = n%400;
                float bias = dir ? (bih_b[jj]+bhh_b[jj]) : (bih_f[jj]+bhh_f[jj]);
                float2 v = unpack2(acc[r][c]);
                int m = m0 + 2*(ty*4 + r);
                float* dst = g_xw + (size_t)dir*GM*400 + (size_t)m*400 + jj;
                dst[0]   = v.x + bias;
                dst[400] = v.y + bias;
            }
        }
}

// ---------------- kernel 3: LSTM recurrence, K-split + xw prefetch -> g_h ----------------
// 128 blocks x 800 thr; thread = (gate j, k-half), half-row whh in regs (52),
// balanced per-half prefetch of own batch's xw. (Frozen: r11/r13 restructures
// both regressed — this is the measured local optimum.)
__global__ __launch_bounds__(800,1) void k_lstm(
    const float* __restrict__ whh_f, const float* __restrict__ whh_b)
{
    int bx  = blockIdx.x;
    int dir = bx >> 6;
    int pr  = bx & 63;
    int b0  = pr*2, b1 = b0+1;
    int tid = threadIdx.x;
    int half = (tid >= 400);
    int j    = half ? tid - 400 : tid;   // gate row 0..399
    int q0   = half ? 13 : 0;            // float4-group offset into h
    int nq   = half ? 12 : 13;
    int bmine = half ? b1 : b0;

    const float* whh = dir ? whh_b : whh_f;
    const ulonglong2* wrow = (const ulonglong2*)(whh + (size_t)j*100);
    ulonglong2 w[13];
#pragma unroll
    for (int q=0;q<13;q++){
        if (q < nq) w[q] = wrow[q0+q];
        else { w[q].x = 0ull; w[q].y = 0ull; }
    }

    __shared__ float h_s[2][112];     // zero-padded; group 25 reads land in zeros
    __shared__ float sp[2][2][400];   // [half][batch][gate]
    if (tid < 224) ((float*)h_s)[tid] = 0.0f;
    float c_reg = 0.0f;

    const float* xw   = g_xw + (size_t)dir*GM*400;
    float*       hout = g_h  + (size_t)dir*GM*100;
    __syncthreads();

    int t0 = dir ? 255 : 0;
    float av = xw[(size_t)(bmine*256+t0)*400 + j];

    for (int step=0; step<256; step++){
        int t = dir ? (255-step) : step;

        float nav = 0.0f;
        if (step < 255){
            int tn = dir ? (254-step) : (step+1);
            nav = xw[(size_t)(bmine*256+tn)*400 + j];
        }

        u64 s0=0ull, s0b=0ull, s1=0ull, s1b=0ull;
#pragma unroll
        for (int q=0;q<13;q++){
            ulonglong2 wq = w[q];
            ulonglong2 h0 = *(const ulonglong2*)&h_s[0][(q0+q)*4];
            ulonglong2 h1 = *(const ulonglong2*)&h_s[1][(q0+q)*4];
            fma2(s0,  wq.x, h0.x);
            fma2(s0b, wq.y, h0.y);
            fma2(s1,  wq.x, h1.x);
            fma2(s1b, wq.y, h1.y);
        }
        float2 u0 = unpack2(s0), u0b = unpack2(s0b);
        float2 u1 = unpack2(s1), u1b = unpack2(s1b);
        float d0 = (u0.x+u0.y)+(u0b.x+u0b.y);
        float d1 = (u1.x+u1.y)+(u1b.x+u1b.y);
        sp[half][0][j] = half ? d0 : d0 + av;
        sp[half][1][j] = half ? d1 + av : d1;
        __syncthreads();

        if (tid < 200){
            int bb = (tid >= 100), k = tid - bb*100;
            float gi = sp[0][bb][k]     + sp[1][bb][k];
            float gf = sp[0][bb][100+k] + sp[1][bb][100+k];
            float gg = sp[0][bb][200+k] + sp[1][bb][200+k];
            float go = sp[0][bb][300+k] + sp[1][bb][300+k];
            float ct = msigm(gf)*c_reg + msigm(gi)*mtanh(gg);
            c_reg = ct;
            float h = msigm(go)*mtanh(ct);
            h_s[bb][k] = h;
            hout[(size_t)((bb?b1:b0)*256+t)*100 + k] = h;
        }
        __syncthreads();
        av = nav;
    }
}

// ---------------- kernel 4: emission projection (tiled) -> g_em ----------------
__global__ __launch_bounds__(256) void k_emis(
    const float* __restrict__ proj_w, const float* __restrict__ proj_b)
{
    __shared__ float hs[64*204];   // [m][k] padded row stride
    __shared__ float pw[200*32];   // [k][tag]
    __shared__ float pb[32];

    int tid = threadIdx.x;
    int bs0 = blockIdx.x*64;

    for (int idx=tid; idx<6400; idx+=256){
        int tag = idx/200, k = idx%200;
        pw[k*32+tag] = proj_w[idx];
    }
    if (tid < 32) pb[tid] = proj_b[tid];

    for (int idx=tid; idx<64*50; idx+=256){
        int m = idx/50, q = idx%50;
        int bs = bs0 + m;
        const float* src = (q < 25) ? (g_h + (size_t)bs*100 + q*4)
                                    : (g_h + (size_t)GM*100 + (size_t)bs*100 + (q-25)*4);
        float4 v = *(const float4*)src;
        *(float4*)&hs[m*204 + q*4] = v;
    }
    __syncthreads();

    int tag  = tid & 31;
    int msub = tid >> 5;           // 0..7

    float acc[8];
#pragma unroll
    for (int i=0;i<8;i++) acc[i] = pb[tag];

    for (int k=0;k<200;k++){
        float pwv = pw[k*32 + tag];
#pragma unroll
        for (int i=0;i<8;i++)
            acc[i] += hs[(msub + 8*i)*204 + k] * pwv;   // broadcast read
    }
#pragma unroll
    for (int i=0;i<8;i++)
        g_em[(size_t)(bs0 + msub + 8*i)*32 + tag] = acc[i];
}

// ---------------- kernel 5: CRF (exp-factorized, lane0-normalized, split sums) ----------------
__global__ __launch_bounds__(32) void k_crf(
    const float* __restrict__ trans, const int* __restrict__ y, float* __restrict__ out)
{
    __shared__ float E_s[32];
    int j = threadIdx.x, b = blockIdx.x;

    float T[32];
#pragma unroll
    for (int i=0;i<32;i++) T[i] = __expf(trans[i*32 + j]);   // exp(NEG)=0, safe
    float tend = trans[j*32 + 31];                           // trans[j, END]

    float score = 0.0f;
    for (int t=j; t<256; t+=32){
        int cur  = y[b*256+t];
        int prev = (t==0) ? 30 : y[b*256+t-1];
        score += g_em[(size_t)(b*256+t)*32 + cur] + trans[prev*32+cur];
    }
    __syncwarp();

    float la  = g_em[(size_t)(b*256)*32 + j] + trans[30*32 + j];
    float emv = g_em[(size_t)(b*256+1)*32 + j];

    for (int t=1; t<256; t++){
        float em_next = (t < 255) ? g_em[(size_t)(b*256+t+1)*32 + j] : 0.0f;

        float m = __shfl_sync(0xffffffffu, la, 0);
        E_s[j] = __expf(la - m);
        __syncwarp();
        float s0=0.f, s1=0.f, s2=0.f, s3=0.f;
#pragma unroll
        for (int i=0;i<8;i++){
            s0 += E_s[i   ]*T[i   ];
            s1 += E_s[i+ 8]*T[i+ 8];
            s2 += E_s[i+16]*T[i+16];
            s3 += E_s[i+24]*T[i+24];
        }
        la = emv + m + __logf((s0+s1)+(s2+s3));
        __syncwarp();
        emv = em_next;
    }

    la += tend;
    float m = la;
#pragma unroll
    for (int o=16;o>0;o>>=1) m = fmaxf(m, __shfl_xor_sync(0xffffffffu, m, o));
    float e = __expf(la - m);
#pragma unroll
    for (int o=16;o>0;o>>=1) e += __shfl_xor_sync(0xffffffffu, e, o);
    float total = m + __logf(e);

#pragma unroll
    for (int o=16;o>0;o>>=1) score += __shfl_xor_sync(0xffffffffu, score, o);

    if (j==0){
        score += trans[y[b*256+255]*32 + 31];
        atomicAdd(out, (total - score) * (1.0f/128.0f));
    }
}

// ---------------- launch ----------------
extern "C" void kernel_launch(void* const* d_in, const int* in_sizes, int n_in,
                              void* d_out, int out_size)
{
    const float* word_emb = (const float*)d_in[0];
    const float* char_emb = (const float*)d_in[1];
    const float* conv_w   = (const float*)d_in[2];
    const float* conv_b   = (const float*)d_in[3];
    const float* wih_f    = (const float*)d_in[4];
    const float* whh_f    = (const float*)d_in[5];
    const float* bih_f    = (const float*)d_in[6];
    const float* bhh_f    = (const float*)d_in[7];
    const float* wih_b    = (const float*)d_in[8];
    const float* whh_b    = (const float*)d_in[9];
    const float* bih_b    = (const float*)d_in[10];
    const float* bhh_b    = (const float*)d_in[11];
    const float* proj_w   = (const float*)d_in[12];
    const float* proj_b   = (const float*)d_in[13];
    const float* trans    = (const float*)d_in[14];
    const int*   word_x   = (const int*)d_in[15];
    const int*   char_x   = (const int*)d_in[16];
    const int*   y        = (const int*)d_in[17];
    float* out = (float*)d_out;

    k_prep<<<(9600+130*800+255)/256,256>>>(conv_w, char_emb, wih_f, wih_b);
    k_cnn<<<512,256>>>(word_emb, conv_b, word_x, char_x);
    dim3 gg(7, 256);
    k_gemm_in<<<gg,256>>>(bih_f, bhh_f, bih_b, bhh_b);
    k_lstm<<<128,800>>>(whh_f, whh_b);
    k_emis<<<512,256>>>(proj_w, proj_b);
    cudaMemsetAsync(out, 0, sizeof(float));
    k_crf<<<128,32>>>(trans, y, out);
}

// round 15
// speedup vs baseline: 2.5631x; 1.1831x over previous
#include <cuda_runtime.h>
#include <cstdint>
#include <cstddef>

#define Bn   128
#define Sn   256
#define GM   (Bn*Sn)         // 32768
#define NEGV (-10000.0f)

typedef unsigned long long u64;

// ---------------- scratch (device globals; no allocation allowed) ----------------
__device__ float g_x [GM*130];            // concat(word_emb, char_feat)
__device__ float g_wt[130*800];           // transposed input weights [k][n]
__device__ float g_xw[2u*GM*400];         // x @ wih^T + (bih+bhh), per direction
__device__ float g_h [2u*GM*100];         // hidden states f/b
__device__ float g_em[GM*32];             // emissions
__device__ float g_P [100*96];            // char-conv table [c][k*32+f]

__device__ __forceinline__ float mtanh(float x){
    float r; asm("tanh.approx.f32 %0, %1;" : "=f"(r) : "f"(x)); return r;
}
__device__ __forceinline__ float msigm(float x){ return fmaf(mtanh(0.5f*x), 0.5f, 0.5f); }

// packed f32x2 helpers (Blackwell; ptxas never auto-fuses these)
__device__ __forceinline__ void fma2(u64 &d, u64 a, u64 b){
    asm("fma.rn.f32x2 %0, %1, %2, %0;" : "+l"(d) : "l"(a), "l"(b));
}
__device__ __forceinline__ u64 pack2(float x, float y){
    u64 r; asm("mov.b64 %0, {%1, %2};" : "=l"(r) : "f"(x), "f"(y)); return r;
}
__device__ __forceinline__ float2 unpack2(u64 v){
    float2 r; asm("mov.b64 {%0, %1}, %2;" : "=f"(r.x), "=f"(r.y) : "l"(v)); return r;
}

__device__ __forceinline__ uint32_t tf32cvt(float x){
    uint32_t r; asm("cvt.rna.tf32.f32 %0, %1;" : "=r"(r) : "f"(x)); return r;
}
__device__ __forceinline__ void mma_tf32(float* c,
    uint32_t a0, uint32_t a1, uint32_t a2, uint32_t a3, uint32_t b0, uint32_t b1)
{
    asm volatile("mma.sync.aligned.m16n8k8.row.col.f32.tf32.tf32.f32 "
        "{%0,%1,%2,%3}, {%4,%5,%6,%7}, {%8,%9}, {%0,%1,%2,%3};"
        : "+f"(c[0]), "+f"(c[1]), "+f"(c[2]), "+f"(c[3])
        : "r"(a0), "r"(a1), "r"(a2), "r"(a3), "r"(b0), "r"(b1));
}

// ---------------- kernel 0: prep = char-conv table + weight transpose ----------------
__global__ __launch_bounds__(256) void k_prep(
    const float* __restrict__ conv_w, const float* __restrict__ char_emb,
    const float* __restrict__ wih_f,  const float* __restrict__ wih_b)
{
    int idx = blockIdx.x*256 + threadIdx.x;
    if (idx < 9600){                              // P table: 100*96
        int c = idx / 96, r = idx % 96, k = r >> 5, f = r & 31;
        float s = 0.0f;
        if (f < 30){
            const float* w = conv_w + f*90 + k*30;
            const float* e = char_emb + c*30;
#pragma unroll
            for (int d=0; d<30; d++) s += w[d]*e[d];
        }
        g_P[idx] = s;
    }
    int idx2 = idx - 9600;                        // wt: 130*800
    if (idx2 >= 0 && idx2 < 130*800){
        int k = idx2 / 800, n = idx2 % 800;
        g_wt[idx2] = (n < 400) ? wih_f[(size_t)n*130 + k] : wih_b[(size_t)(n-400)*130 + k];
    }
}

// ---------------- kernel 1: embedding concat + table-lookup char CNN -> g_x ----------------
__global__ __launch_bounds__(256) void k_cnn(
    const float* __restrict__ word_emb, const float* __restrict__ conv_b,
    const int*   __restrict__ word_x,   const int*   __restrict__ char_x)
{
    __shared__ float sP[9600];
    __shared__ float sb[32];

    int tid  = threadIdx.x;
    int lane = tid & 31;
    int wrp  = tid >> 5;

    for (int i = tid; i < 9600; i += 256) sP[i] = g_P[i];
    if (tid < 30) sb[tid] = conv_b[tid];
    __syncthreads();

    int base = blockIdx.x*64 + wrp*8;
#pragma unroll
    for (int i=0;i<8;i++){
        int bs = base + i;

        int cv = 0;
        if (lane < 10) cv = char_x[bs*10 + lane];

        int wid = word_x[bs];
        const float* wrow = word_emb + (size_t)wid*100;
        float* xo = g_x + (size_t)bs*130;
        for (int t = lane; t < 100; t += 32) xo[t] = wrow[t];

        int ci[10];
#pragma unroll
        for (int l=0;l<10;l++)
            ci[l] = __shfl_sync(0xffffffffu, cv, l)*96 + lane;

        float best = -1e30f;
#pragma unroll
        for (int p=0;p<12;p++){
            float acc = 0.0f;
            if (p >= 2)           acc += sP[ci[p-2] +  0];
            if (p >= 1 && p <=10) acc += sP[ci[p-1] + 32];
            if (p <= 9)           acc += sP[ci[p]   + 64];
            best = fmaxf(best, acc);
        }
        if (lane < 30) xo[100 + lane] = best + sb[lane];
    }
}

// ---------------- kernel 2: input-projection GEMM, tf32 mma.sync -> g_xw ----------------
// Block 128(m) x 64(n), 256 thr (8 warps, 2x4 warp grid), 3 blocks/SM.
// K split into 5 chunks of 32 (last: 2 real k, zero-padded).
// A smem [m][k] stride 36 (bank (4g+tg)%32, conflict-free fragment loads).
// B smem [k][n] n-width 72 (bank (8k+n)%32, conflict-free fragment loads).
// tf32 rounding applied once at staging (cvt.rna).
__global__ __launch_bounds__(256,3) void k_gemm_in(
    const float* __restrict__ bih_f, const float* __restrict__ bhh_f,
    const float* __restrict__ bih_b, const float* __restrict__ bhh_b)
{
    __shared__ uint32_t As[128*36];   // 18.4 KB
    __shared__ uint32_t Bs[32*72];    //  9.2 KB

    int tid  = threadIdx.x;
    int m0   = blockIdx.y*128;
    int n0   = blockIdx.x*64;
    int w    = tid >> 5;
    int lane = tid & 31;
    int g    = lane >> 2, tg = lane & 3;
    int wm   = w >> 2,  wn = w & 3;    // 2 (m) x 4 (n) warps

    float acc[4][2][4];                // [mtile][ntile][c0..c3]
#pragma unroll
    for (int i=0;i<4;i++)
#pragma unroll
        for (int jj=0;jj<2;jj++)
#pragma unroll
            for (int q=0;q<4;q++) acc[i][jj][q] = 0.0f;

    for (int c=0; c<5; c++){
        int kb   = c*32;
        int klen = (c < 4) ? 32 : 2;

        // stage A (LDG coalesced along k; STS sequential)
        for (int idx=tid; idx<128*32; idx+=256){
            int m = idx >> 5, k = idx & 31;
            float v = (k < klen) ? g_x[(size_t)(m0+m)*130 + kb + k] : 0.0f;
            As[m*36 + k] = tf32cvt(v);
        }
        // stage B (LDG coalesced along n; STS sequential)
        for (int idx=tid; idx<32*64; idx+=256){
            int k = idx >> 6, n = idx & 63;
            int gn = n0 + n;
            float v = (k < klen && gn < 800) ? g_wt[(size_t)(kb+k)*800 + gn] : 0.0f;
            Bs[k*72 + n] = tf32cvt(v);
        }
        __syncthreads();

        int nks = (c < 4) ? 4 : 1;
#pragma unroll
        for (int ks=0; ks<4; ks++){
            if (ks >= nks) break;
            int k = ks*8;
            uint32_t af[4][4];
#pragma unroll
            for (int i=0;i<4;i++){
                int r0 = wm*64 + i*16 + g;
                af[i][0] = As[ r0    *36 + k + tg    ];
                af[i][1] = As[(r0+8) *36 + k + tg    ];
                af[i][2] = As[ r0    *36 + k + tg + 4];
                af[i][3] = As[(r0+8) *36 + k + tg + 4];
            }
            uint32_t bf[2][2];
#pragma unroll
            for (int jj=0;jj<2;jj++){
                int col = wn*16 + jj*8 + g;
                bf[jj][0] = Bs[(k + tg    )*72 + col];
                bf[jj][1] = Bs[(k + tg + 4)*72 + col];
            }
#pragma unroll
            for (int i=0;i<4;i++)
#pragma unroll
                for (int jj=0;jj<2;jj++)
                    mma_tf32(acc[i][jj], af[i][0], af[i][1], af[i][2], af[i][3],
                             bf[jj][0], bf[jj][1]);
        }
        __syncthreads();
    }

    // epilogue: c0->(m,n), c1->(m,n+1), c2->(m+8,n), c3->(m+8,n+1)
#pragma unroll
    for (int i=0;i<4;i++)
#pragma unroll
        for (int jj=0;jj<2;jj++){
            int m = m0 + wm*64 + i*16 + g;
            int n = n0 + wn*16 + jj*8 + tg*2;
            if (n < 800){
                int dir = n/400, j0 = n%400;
                float bia0 = dir ? (bih_b[j0  ]+bhh_b[j0  ]) : (bih_f[j0  ]+bhh_f[j0  ]);
                float bia1 = dir ? (bih_b[j0+1]+bhh_b[j0+1]) : (bih_f[j0+1]+bhh_f[j0+1]);
                float* d0 = g_xw + (size_t)dir*GM*400 + (size_t)m*400 + j0;
                *(float2*)d0            = make_float2(acc[i][jj][0]+bia0, acc[i][jj][1]+bia1);
                *(float2*)(d0 + 8*400)  = make_float2(acc[i][jj][2]+bia0, acc[i][jj][3]+bia1);
            }
        }
}

// ---------------- kernel 3: LSTM recurrence, K-split + xw prefetch -> g_h ----------------
// (Frozen at the measured local optimum: r11/r13 restructures both regressed.)
__global__ __launch_bounds__(800,1) void k_lstm(
    const float* __restrict__ whh_f, const float* __restrict__ whh_b)
{
    int bx  = blockIdx.x;
    int dir = bx >> 6;
    int pr  = bx & 63;
    int b0  = pr*2, b1 = b0+1;
    int tid = threadIdx.x;
    int half = (tid >= 400);
    int j    = half ? tid - 400 : tid;   // gate row 0..399
    int q0   = half ? 13 : 0;            // float4-group offset into h
    int nq   = half ? 12 : 13;
    int bmine = half ? b1 : b0;

    const float* whh = dir ? whh_b : whh_f;
    const ulonglong2* wrow = (const ulonglong2*)(whh + (size_t)j*100);
    ulonglong2 w[13];
#pragma unroll
    for (int q=0;q<13;q++){
        if (q < nq) w[q] = wrow[q0+q];
        else { w[q].x = 0ull; w[q].y = 0ull; }
    }

    __shared__ float h_s[2][112];     // zero-padded; group 25 reads land in zeros
    __shared__ float sp[2][2][400];   // [half][batch][gate]
    if (tid < 224) ((float*)h_s)[tid] = 0.0f;
    float c_reg = 0.0f;

    const float* xw   = g_xw + (size_t)dir*GM*400;
    float*       hout = g_h  + (size_t)dir*GM*100;
    __syncthreads();

    int t0 = dir ? 255 : 0;
    float av = xw[(size_t)(bmine*256+t0)*400 + j];

    for (int step=0; step<256; step++){
        int t = dir ? (255-step) : step;

        float nav = 0.0f;
        if (step < 255){
            int tn = dir ? (254-step) : (step+1);
            nav = xw[(size_t)(bmine*256+tn)*400 + j];
        }

        u64 s0=0ull, s0b=0ull, s1=0ull, s1b=0ull;
#pragma unroll
        for (int q=0;q<13;q++){
            ulonglong2 wq = w[q];
            ulonglong2 h0 = *(const ulonglong2*)&h_s[0][(q0+q)*4];
            ulonglong2 h1 = *(const ulonglong2*)&h_s[1][(q0+q)*4];
            fma2(s0,  wq.x, h0.x);
            fma2(s0b, wq.y, h0.y);
            fma2(s1,  wq.x, h1.x);
            fma2(s1b, wq.y, h1.y);
        }
        float2 u0 = unpack2(s0), u0b = unpack2(s0b);
        float2 u1 = unpack2(s1), u1b = unpack2(s1b);
        float d0 = (u0.x+u0.y)+(u0b.x+u0b.y);
        float d1 = (u1.x+u1.y)+(u1b.x+u1b.y);
        sp[half][0][j] = half ? d0 : d0 + av;
        sp[half][1][j] = half ? d1 + av : d1;
        __syncthreads();

        if (tid < 200){
            int bb = (tid >= 100), k = tid - bb*100;
            float gi = sp[0][bb][k]     + sp[1][bb][k];
            float gf = sp[0][bb][100+k] + sp[1][bb][100+k];
            float gg = sp[0][bb][200+k] + sp[1][bb][200+k];
            float go = sp[0][bb][300+k] + sp[1][bb][300+k];
            float ct = msigm(gf)*c_reg + msigm(gi)*mtanh(gg);
            c_reg = ct;
            float h = msigm(go)*mtanh(ct);
            h_s[bb][k] = h;
            hout[(size_t)((bb?b1:b0)*256+t)*100 + k] = h;
        }
        __syncthreads();
        av = nav;
    }
}

// ---------------- kernel 4: emission projection (tiled) -> g_em ----------------
__global__ __launch_bounds__(256) void k_emis(
    const float* __restrict__ proj_w, const float* __restrict__ proj_b)
{
    __shared__ float hs[64*204];   // [m][k] padded row stride
    __shared__ float pw[200*32];   // [k][tag]
    __shared__ float pb[32];

    int tid = threadIdx.x;
    int bs0 = blockIdx.x*64;

    for (int idx=tid; idx<6400; idx+=256){
        int tag = idx/200, k = idx%200;
        pw[k*32+tag] = proj_w[idx];
    }
    if (tid < 32) pb[tid] = proj_b[tid];

    for (int idx=tid; idx<64*50; idx+=256){
        int m = idx/50, q = idx%50;
        int bs = bs0 + m;
        const float* src = (q < 25) ? (g_h + (size_t)bs*100 + q*4)
                                    : (g_h + (size_t)GM*100 + (size_t)bs*100 + (q-25)*4);
        float4 v = *(const float4*)src;
        *(float4*)&hs[m*204 + q*4] = v;
    }
    __syncthreads();

    int tag  = tid & 31;
    int msub = tid >> 5;           // 0..7

    float acc[8];
#pragma unroll
    for (int i=0;i<8;i++) acc[i] = pb[tag];

    for (int k=0;k<200;k++){
        float pwv = pw[k*32 + tag];
#pragma unroll
        for (int i=0;i<8;i++)
            acc[i] += hs[(msub + 8*i)*204 + k] * pwv;   // broadcast read
    }
#pragma unroll
    for (int i=0;i<8;i++)
        g_em[(size_t)(bs0 + msub + 8*i)*32 + tag] = acc[i];
}

// ---------------- kernel 5: CRF (exp-factorized, lane0-normalized, split sums) ----------------
__global__ __launch_bounds__(32) void k_crf(
    const float* __restrict__ trans, const int* __restrict__ y, float* __restrict__ out)
{
    __shared__ float E_s[32];
    int j = threadIdx.x, b = blockIdx.x;

    float T[32];
#pragma unroll
    for (int i=0;i<32;i++) T[i] = __expf(trans[i*32 + j]);   // exp(NEG)=0, safe
    float tend = trans[j*32 + 31];                           // trans[j, END]

    float score = 0.0f;
    for (int t=j; t<256; t+=32){
        int cur  = y[b*256+t];
        int prev = (t==0) ? 30 : y[b*256+t-1];
        score += g_em[(size_t)(b*256+t)*32 + cur] + trans[prev*32+cur];
    }
    __syncwarp();

    float la  = g_em[(size_t)(b*256)*32 + j] + trans[30*32 + j];
    float emv = g_em[(size_t)(b*256+1)*32 + j];

    for (int t=1; t<256; t++){
        float em_next = (t < 255) ? g_em[(size_t)(b*256+t+1)*32 + j] : 0.0f;

        float m = __shfl_sync(0xffffffffu, la, 0);
        E_s[j] = __expf(la - m);
        __syncwarp();
        float s0=0.f, s1=0.f, s2=0.f, s3=0.f;
#pragma unroll
        for (int i=0;i<8;i++){
            s0 += E_s[i   ]*T[i   ];
            s1 += E_s[i+ 8]*T[i+ 8];
            s2 += E_s[i+16]*T[i+16];
            s3 += E_s[i+24]*T[i+24];
        }
        la = emv + m + __logf((s0+s1)+(s2+s3));
        __syncwarp();
        emv = em_next;
    }

    la += tend;
    float m = la;
#pragma unroll
    for (int o=16;o>0;o>>=1) m = fmaxf(m, __shfl_xor_sync(0xffffffffu, m, o));
    float e = __expf(la - m);
#pragma unroll
    for (int o=16;o>0;o>>=1) e += __shfl_xor_sync(0xffffffffu, e, o);
    float total = m + __logf(e);

#pragma unroll
    for (int o=16;o>0;o>>=1) score += __shfl_xor_sync(0xffffffffu, score, o);

    if (j==0){
        score += trans[y[b*256+255]*32 + 31];
        atomicAdd(out, (total - score) * (1.0f/128.0f));
    }
}

// ---------------- launch ----------------
extern "C" void kernel_launch(void* const* d_in, const int* in_sizes, int n_in,
                              void* d_out, int out_size)
{
    const float* word_emb = (const float*)d_in[0];
    const float* char_emb = (const float*)d_in[1];
    const float* conv_w   = (const float*)d_in[2];
    const float* conv_b   = (const float*)d_in[3];
    const float* wih_f    = (const float*)d_in[4];
    const float* whh_f    = (const float*)d_in[5];
    const float* bih_f    = (const float*)d_in[6];
    const float* bhh_f    = (const float*)d_in[7];
    const float* wih_b    = (const float*)d_in[8];
    const float* whh_b    = (const float*)d_in[9];
    const float* bih_b    = (const float*)d_in[10];
    const float* bhh_b    = (const float*)d_in[11];
    const float* proj_w   = (const float*)d_in[12];
    const float* proj_b   = (const float*)d_in[13];
    const float* trans    = (const float*)d_in[14];
    const int*   word_x   = (const int*)d_in[15];
    const int*   char_x   = (const int*)d_in[16];
    const int*   y        = (const int*)d_in[17];
    float* out = (float*)d_out;

    k_prep<<<(9600+130*800+255)/256,256>>>(conv_w, char_emb, wih_f, wih_b);
    k_cnn<<<512,256>>>(word_emb, conv_b, word_x, char_x);
    dim3 gg(13, 256);
    k_gemm_in<<<gg,256>>>(bih_f, bhh_f, bih_b, bhh_b);
    k_lstm<<<128,800>>>(whh_f, whh_b);
    k_emis<<<512,256>>>(proj_w, proj_b);
    cudaMemsetAsync(out, 0, sizeof(float));
    k_crf<<<128,32>>>(trans, y, out);
}